// round 6
// baseline (speedup 1.0000x reference)
#include <cuda_runtime.h>

#define NB 4
#define LL 4096
#define ND 8
#define KMAX 64
#define NCODES 256

#define NBUILD 128           // builder blocks
#define NEMIT  512           // emit blocks
#define NBLK   (NBUILD + NEMIT)

// Scratch (no allocations): per-(batch,code) rows (float32) + gate counters.
__device__ float g_rows[NB * NCODES * KMAX];
__device__ int   g_ready;    // builders done count (zero-init, self-reset)
__device__ int   g_done;     // emit blocks done count (zero-init, self-reset)

__device__ __forceinline__ int pack8(float4 a, float4 c) {
    return (a.x > 0.f)        | ((a.y > 0.f) << 1) |
           ((a.z > 0.f) << 2) | ((a.w > 0.f) << 3) |
           ((c.x > 0.f) << 4) | ((c.y > 0.f) << 5) |
           ((c.z > 0.f) << 6) | ((c.w > 0.f) << 7);
}

// Fused kernel. Blocks 0..127: build rows (one warp per (batch,code), stable
// first-64 ballot scan). Blocks 128..639: emit (4 queries/warp); query loads
// and code packing happen BEFORE the gate, overlapping the build phase.
__global__ void __launch_bounds__(256, 8)
k_fused(const float* __restrict__ key_up,
        const float* __restrict__ query_up,
        float* __restrict__ out) {
    __shared__ int4 sc4[LL / 4];    // 16 KB (builder only uses it)
    __shared__ int  buf[8][KMAX];

    int tid  = threadIdx.x;
    int warp = tid >> 5;
    int lane = tid & 31;

    if (blockIdx.x < NBUILD) {
        // ----------------- builder -----------------
        int b  = blockIdx.x >> 5;
        int cg = blockIdx.x & 31;
        int* sc = reinterpret_cast<int*>(sc4);

        const float4* kb = reinterpret_cast<const float4*>(key_up + (size_t)b * LL * ND);
        #pragma unroll
        for (int it = 0; it < 16; it++) {
            int j = tid + it * 256;
            sc[j] = pack8(kb[j * 2], kb[j * 2 + 1]);
        }
        __syncthreads();

        int c = cg * 8 + warp;
        unsigned lt = (1u << lane) - 1u;
        int m = 0;
        #pragma unroll 4
        for (int r = 0; r < 32; r++) {
            int4 v = sc4[r * 32 + lane];
            unsigned m0 = __ballot_sync(0xffffffffu, v.x == c);
            unsigned m1 = __ballot_sync(0xffffffffu, v.y == c);
            unsigned m2 = __ballot_sync(0xffffffffu, v.z == c);
            unsigned m3 = __ballot_sync(0xffffffffu, v.w == c);
            int p = m + __popc(m0 & lt) + __popc(m1 & lt)
                      + __popc(m2 & lt) + __popc(m3 & lt);
            int j0 = (r * 32 + lane) * 4;
            if (v.x == c) { if (p < KMAX) buf[warp][p] = j0;     p++; }
            if (v.y == c) { if (p < KMAX) buf[warp][p] = j0 + 1; p++; }
            if (v.z == c) { if (p < KMAX) buf[warp][p] = j0 + 2; p++; }
            if (v.w == c) { if (p < KMAX) buf[warp][p] = j0 + 3; p++; }
            m += __popc(m0) + __popc(m1) + __popc(m2) + __popc(m3);
        }
        __syncwarp();

        int mm  = m < KMAX ? m : KMAX;
        int pad = KMAX - mm;
        float* row = g_rows + (((b << 8) + c) * KMAX);
        #pragma unroll
        for (int k = lane; k < KMAX; k += 32)
            row[k] = (k < pad) ? -1.0f : (float)buf[warp][k - pad];

        __syncthreads();                  // all 8 rows of this block written
        if (tid == 0) {
            __threadfence();              // release rows
            atomicAdd(&g_ready, 1);
        }
    } else {
        // ----------------- emit -----------------
        int eb = blockIdx.x - NBUILD;            // 0..511
        int gw = eb * 8 + warp;                  // warp id 0..4095

        // Pre-gate: load queries + pack codes (overlaps the build phase).
        int code = 0;
        if (lane < 4) {
            const float4* p = reinterpret_cast<const float4*>(query_up)
                              + (gw * 4 + lane) * 2;
            code = pack8(p[0], p[1]);
        }

        // Gate: wait for all 128 builder blocks.
        if (tid == 0) {
            while (atomicAdd(&g_ready, 0) < NBUILD) __nanosleep(128);
        }
        __syncthreads();                  // gate + acquire for the block

        int g  = lane >> 3;                      // group 0..3
        int c  = __shfl_sync(0xffffffffu, code, g);
        int qi = gw * 4 + g;                     // query id
        int b  = qi >> 12;                       // / 4096

        const float4* src = reinterpret_cast<const float4*>(
            g_rows + (((b << 8) + c) * KMAX));
        float4* dst = reinterpret_cast<float4*>(out + (size_t)qi * KMAX);
        int o = lane & 7;                        // 8 lanes x 2 float4 = 256B
        float4 v0 = src[o];
        float4 v1 = src[o + 8];
        dst[o]     = v0;
        dst[o + 8] = v1;

        // Self-reset so the next graph replay starts from zeroed counters.
        __syncthreads();
        if (tid == 0) {
            int d = atomicAdd(&g_done, 1);
            if (d == NEMIT - 1) {         // last emit block: everyone passed
                atomicExch(&g_ready, 0);
                atomicExch(&g_done, 0);
            }
        }
    }
}

extern "C" void kernel_launch(void* const* d_in, const int* in_sizes, int n_in,
                              void* d_out, int out_size) {
    // Identify inputs by element count (robust to metadata ordering).
    const float* query_up = nullptr;
    const float* key_up   = nullptr;
    for (int i = 0; i < n_in; i++) {
        if (in_sizes[i] == NB * LL * ND) {
            if (!query_up)      query_up = (const float*)d_in[i];
            else if (!key_up)   key_up   = (const float*)d_in[i];
        }
    }
    if (!query_up || !key_up) {
        query_up = (const float*)d_in[0];
        key_up   = (const float*)d_in[1];
    }
    float* out = (float*)d_out;

    k_fused<<<NBLK, 256>>>(key_up, query_up, out);
}

// round 7
// speedup vs baseline: 1.3175x; 1.3175x over previous
#include <cuda_runtime.h>

#define NB 4
#define LL 4096
#define ND 8
#define KMAX 64
#define NCODES 256
#define BIGV 65535

// Scratch (no allocations). g_cnt is zero-initialized and self-reset by k_rank
// every run, so graph replays are deterministic.
__device__ float          g_rows [NB * NCODES * KMAX];   // 256 KB
__device__ int            g_cnt  [NB * NCODES];          // 4 KB
__device__ unsigned short g_tmp  [NB * NCODES * KMAX];   // 128 KB buckets
__device__ unsigned char  g_codes[NB * LL];              // 16 KB (overflow path)

__device__ __forceinline__ int pack8(float4 a, float4 c) {
    return (a.x > 0.f)        | ((a.y > 0.f) << 1) |
           ((a.z > 0.f) << 2) | ((a.w > 0.f) << 3) |
           ((c.x > 0.f) << 4) | ((c.y > 0.f) << 5) |
           ((c.z > 0.f) << 6) | ((c.w > 0.f) << 7);
}

// K1: one thread per key. Pack code, scatter index into (batch,code) bucket.
__global__ void k_scatter(const float* __restrict__ key_up) {
    int t = blockIdx.x * blockDim.x + threadIdx.x;       // 0..16383
    const float4* p = reinterpret_cast<const float4*>(key_up) + t * 2;
    int code = pack8(p[0], p[1]);
    g_codes[t] = (unsigned char)code;
    int b = t >> 12, j = t & (LL - 1);
    int cidx = (b << 8) | code;
    int pos = atomicAdd(&g_cnt[cidx], 1);
    if (pos < KMAX) g_tmp[cidx * KMAX + pos] = (unsigned short)j;
}

// K2: one warp per (batch,code). Rank-sort the <=64 bucket entries (distinct j,
// arbitrary arrival order) into the padded ascending row:
// (64-n) leading -1s then the n indices ascending. Resets the counter.
__global__ void k_rank() {
    int gw   = (blockIdx.x * blockDim.x + threadIdx.x) >> 5;  // 0..1023 = cidx
    int lane = threadIdx.x & 31;
    int n    = g_cnt[gw];
    float* row = g_rows + gw * KMAX;

    if (n <= KMAX) {
        int v0 = (lane      < n) ? (int)g_tmp[gw * KMAX + lane]      : BIGV;
        int v1 = (lane + 32 < n) ? (int)g_tmp[gw * KMAX + lane + 32] : BIGV;
        int r0 = 0, r1 = 0;
        #pragma unroll
        for (int k = 0; k < 32; k++) {
            int u0 = __shfl_sync(0xffffffffu, v0, k);
            int u1 = __shfl_sync(0xffffffffu, v1, k);
            r0 += (u0 < v0) + (u1 < v0);
            r1 += (u0 < v1) + (u1 < v1);
        }
        int pad = KMAX - n;
        // All target positions are disjoint: k<pad get -1, ranks cover pad..63.
        if (lane      < pad) row[lane]      = -1.0f;
        if (lane + 32 < pad) row[lane + 32] = -1.0f;
        if (v0 != BIGV) row[pad + r0] = (float)v0;
        if (v1 != BIGV) row[pad + r1] = (float)v1;
    } else {
        // Overflow (>64 matches): bucket kept an arbitrary subset -> redo this
        // code with a stable ballot scan (first 64 ascending; pad = 0).
        int b = gw >> 8, c = gw & 255;
        const uchar4* cc = reinterpret_cast<const uchar4*>(g_codes + b * LL);
        unsigned lt = (1u << lane) - 1u;
        int m = 0;
        for (int r = 0; r < 32 && m < KMAX; r++) {
            uchar4 v = cc[r * 32 + lane];
            unsigned m0 = __ballot_sync(0xffffffffu, v.x == c);
            unsigned m1 = __ballot_sync(0xffffffffu, v.y == c);
            unsigned m2 = __ballot_sync(0xffffffffu, v.z == c);
            unsigned m3 = __ballot_sync(0xffffffffu, v.w == c);
            int p = m + __popc(m0 & lt) + __popc(m1 & lt)
                      + __popc(m2 & lt) + __popc(m3 & lt);
            int j0 = (r * 32 + lane) * 4;
            if (v.x == c) { if (p < KMAX) row[p] = (float)j0;       p++; }
            if (v.y == c) { if (p < KMAX) row[p] = (float)(j0 + 1); p++; }
            if (v.z == c) { if (p < KMAX) row[p] = (float)(j0 + 2); p++; }
            if (v.w == c) { if (p < KMAX) row[p] = (float)(j0 + 3); p++; }
            m += __popc(m0) + __popc(m1) + __popc(m2) + __popc(m3);
        }
    }
    if (lane == 0) g_cnt[gw] = 0;   // self-reset for the next graph replay
}

// K3: 16 queries per warp. Every lane loads one float4 (512B coalesced query
// read per warp); nibble pairs combine via shfl_xor into 8-bit codes; each
// lane copies half a row (8x float4, deep MLP) to the output.
__global__ void k_emit(const float* __restrict__ query_up,
                       float* __restrict__ out) {
    int gw   = (blockIdx.x * blockDim.x + threadIdx.x) >> 5;  // 0..1023
    int lane = threadIdx.x & 31;

    float4 p = reinterpret_cast<const float4*>(query_up)[gw * 32 + lane];
    int nib = (p.x > 0.f)        | ((p.y > 0.f) << 1) |
              ((p.z > 0.f) << 2) | ((p.w > 0.f) << 3);
    int partner = __shfl_xor_sync(0xffffffffu, nib, 1);
    int code = (lane & 1) ? (partner | (nib << 4)) : (nib | (partner << 4));

    int qi = gw * 16 + (lane >> 1);          // query id
    int b  = gw >> 8;                        // 256 warps per batch
    int h  = (lane & 1) * 8;                 // which half of the 256B row

    const float4* src = reinterpret_cast<const float4*>(g_rows)
                        + (((b << 8) + code) * 16) + h;
    float4* dst = reinterpret_cast<float4*>(out) + qi * 16 + h;

    float4 v[8];
    #pragma unroll
    for (int t = 0; t < 8; t++) v[t] = src[t];
    #pragma unroll
    for (int t = 0; t < 8; t++) dst[t] = v[t];
}

extern "C" void kernel_launch(void* const* d_in, const int* in_sizes, int n_in,
                              void* d_out, int out_size) {
    // Identify inputs by element count (robust to metadata ordering).
    const float* query_up = nullptr;
    const float* key_up   = nullptr;
    for (int i = 0; i < n_in; i++) {
        if (in_sizes[i] == NB * LL * ND) {
            if (!query_up)      query_up = (const float*)d_in[i];
            else if (!key_up)   key_up   = (const float*)d_in[i];
        }
    }
    if (!query_up || !key_up) {
        query_up = (const float*)d_in[0];
        key_up   = (const float*)d_in[1];
    }
    float* out = (float*)d_out;

    k_scatter<<<64, 256>>>(key_up);          // 16384 threads, 1 key each
    k_rank<<<128, 256>>>();                  // 1024 warps, 1 (b,code) each
    k_emit<<<128, 256>>>(query_up, out);     // 1024 warps, 16 queries each
}